// round 8
// baseline (speedup 1.0000x reference)
#include <cuda_runtime.h>
#include <math.h>

#define NPTS   2048
#define IDIM   16
#define HDIM   32
#define JSPLIT 9
#define JCHUNK 228          // 8*228 + 224 = 2048 (always even)
#define TILE_I 128

typedef unsigned long long ull;

// ---------------- device scratch ----------------
__device__ float4 g_pts4[NPTS];
__device__ float4 g_nrm4[NPTS];
__device__ float  g_z   [NPTS * HDIM];
__device__ float  g_mid [NPTS * HDIM];
__device__ float  g_partial[JSPLIT][NPTS * HDIM];
__device__ float  g_stats[8];   // mu[0..3], rstd[4..7]

__device__ __forceinline__ float leakyf(float x) { return x >= 0.f ? x : 0.2f * x; }

// ---------------- packed f32x2 (native 64-bit regs, sm_103a) ----------------
__device__ __forceinline__ ull fma2(ull a, ull b, ull c) {
    ull d; asm("fma.rn.f32x2 %0, %1, %2, %3;" : "=l"(d) : "l"(a), "l"(b), "l"(c)); return d;
}
__device__ __forceinline__ ull add2(ull a, ull b) {
    ull d; asm("add.rn.f32x2 %0, %1, %2;" : "=l"(d) : "l"(a), "l"(b)); return d;
}
__device__ __forceinline__ ull mul2(ull a, ull b) {
    ull d; asm("mul.rn.f32x2 %0, %1, %2;" : "=l"(d) : "l"(a), "l"(b)); return d;
}
__device__ __forceinline__ ull negsign2(ull a) {   // flip both sign bits (ALU pipe)
    ull d; asm("xor.b64 %0, %1, 0x8000000080000000;" : "=l"(d) : "l"(a)); return d;
}
__device__ __forceinline__ ull pack2(float lo, float hi) {
    ull d; asm("mov.b64 %0, {%1, %2};" : "=l"(d) : "f"(lo), "f"(hi)); return d;
}
__device__ __forceinline__ float2 unpack2(ull a) {
    float2 v; asm("mov.b64 {%0, %1}, %2;" : "=f"(v.x), "=f"(v.y) : "l"(a)); return v;
}
__device__ __forceinline__ ull relu2(ull a) {      // 2x FMNMX (ALU pipe)
    float2 v = unpack2(a);
    v.x = fmaxf(v.x, 0.f);
    v.y = fmaxf(v.y, 0.f);
    return pack2(v.x, v.y);
}

// ---------------- net_in: warp per point + prep ----------------
__global__ void k_netin(const float* __restrict__ points, const float* __restrict__ nuv,
                        const float* __restrict__ x,
                        const float* __restrict__ W1, const float* __restrict__ b1,
                        const float* __restrict__ W2, const float* __restrict__ b2) {
    __shared__ float sW1t[IDIM * HDIM];   // [c][h]
    __shared__ float sW2t[HDIM * HDIM];   // [c][h]
    __shared__ float sb1[HDIM], sb2[HDIM];
    int tid = threadIdx.x;
    for (int k = tid; k < HDIM * IDIM; k += 256) {
        int h = k / IDIM, c = k % IDIM;
        sW1t[c * HDIM + h] = W1[k];
    }
    for (int k = tid; k < HDIM * HDIM; k += 256) {
        int h = k >> 5, c = k & 31;
        sW2t[c * HDIM + h] = W2[k];
    }
    if (tid < HDIM) { sb1[tid] = b1[tid]; sb2[tid] = b2[tid]; }
    __syncthreads();

    int n    = blockIdx.x * 8 + (tid >> 5);
    int lane = tid & 31;

    if (lane == 0) {
        const float s = 0.07856742013183862f;  // 1/(sqrt(2)*9)
        g_pts4[n] = make_float4(points[n*3] * s, points[n*3+1] * s, points[n*3+2] * s, 0.f);
        g_nrm4[n] = make_float4(nuv[n*9], nuv[n*9+1], nuv[n*9+2], 0.f);
    }

    float xi = (lane < IDIM) ? x[n * IDIM + lane] : 0.f;

    float acc = sb1[lane];
#pragma unroll
    for (int c = 0; c < IDIM; c++)
        acc = fmaf(sW1t[c * HDIM + lane], __shfl_sync(0xffffffffu, xi, c), acc);
    float z1 = leakyf(acc);

    acc = sb2[lane];
#pragma unroll
    for (int c = 0; c < HDIM; c++)
        acc = fmaf(sW2t[c * HDIM + lane], __shfl_sync(0xffffffffu, z1, c), acc);
    g_z[n * HDIM + lane] = leakyf(acc);
}

// ---------------- group-norm stats (fp32 inner, fp64 final) ----------------
__global__ void k_gstats(const float* __restrict__ z) {
    __shared__ float sh_s[1024], sh_q[1024];
    __shared__ double sd_s[32], sd_q[32];
    int tid = threadIdx.x;
    int c = tid & 31;
    int r0 = tid >> 5;
    float s = 0.f, q = 0.f;
    for (int it = 0; it < NPTS / 32; it++) {
        float v = z[(r0 + 32 * it) * HDIM + c];
        s += v;
        q = fmaf(v, v, q);
    }
    sh_s[tid] = s; sh_q[tid] = q;
    __syncthreads();
    if (tid < 32) {
        double S = 0.0, Q = 0.0;
        for (int m = 0; m < 32; m++) { S += (double)sh_s[tid + 32 * m]; Q += (double)sh_q[tid + 32 * m]; }
        sd_s[tid] = S; sd_q[tid] = Q;
    }
    __syncthreads();
    if (tid < 4) {
        double S = 0.0, Q = 0.0;
        for (int cc = tid * 8; cc < tid * 8 + 8; cc++) { S += sd_s[cc]; Q += sd_q[cc]; }
        double cntd = (double)NPTS * 8.0;
        double mu = S / cntd;
        double var = Q / cntd - mu * mu;
        g_stats[tid]     = (float)mu;
        g_stats[4 + tid] = (float)(1.0 / sqrt(var + 1e-5));
    }
}

// ---------------- apply group norm (final output) ----------------
__global__ void k_gnorm(const float* __restrict__ z, const float* __restrict__ gamma,
                        const float* __restrict__ beta, float* __restrict__ out) {
    int idx = blockIdx.x * blockDim.x + threadIdx.x;
    if (idx >= NPTS * HDIM) return;
    int c = idx & (HDIM - 1);
    int g = c >> 3;
    out[idx] = (z[idx] - g_stats[g]) * g_stats[4 + g] * gamma[c] + beta[c];
}

// ---------------- pairwise interaction: j-pair-packed preamble, A2 in regs ----------------
__global__ void __launch_bounds__(TILE_I, 2)
k_pair(const float* __restrict__ nuv,
       const float* __restrict__ A1, const float* __restrict__ B1,
       const float* __restrict__ A2, const float* __restrict__ B2,
       const float* __restrict__ gamma, const float* __restrict__ beta) {
    __shared__ ull sPx[JCHUNK/2], sPy[JCHUNK/2], sPz[JCHUNK/2];
    __shared__ ull sNx[JCHUNK/2], sNy[JCHUNK/2], sNz[JCHUNK/2];
    __shared__ __align__(16) float sF[JCHUNK][HDIM];
    __shared__ ull sA1p[16];        // a1x[0..3], a1y[4..7], a1z[8..11], b1p[12..15]
    __shared__ float smu[4], srs[4];

    int tid = threadIdx.x;
    int j0  = blockIdx.y * JCHUNK;
    int cnt = min(JCHUNK, NPTS - j0);   // always even (228 or 224)
    int npairs = cnt >> 1;

    if (tid < 4) { smu[tid] = g_stats[tid]; srs[tid] = g_stats[4 + tid]; }
    if (tid >= 16 && tid < 32) {   // A1/B1 packed across cut pairs
        int k = tid - 16;
        int comp = k >> 2, q = k & 3;
        int c0 = 2 * q, c1 = 2 * q + 1;
        sA1p[k] = (comp < 3) ? pack2(A1[c0 * 3 + comp], A1[c1 * 3 + comp])
                             : pack2(B1[c0], B1[c1]);
    }
    __syncthreads();   // smu/srs before sF fill

    for (int k = tid; k < npairs; k += TILE_I) {
        float4 pa = g_pts4[j0 + 2*k], pb = g_pts4[j0 + 2*k + 1];
        float4 na = g_nrm4[j0 + 2*k], nb = g_nrm4[j0 + 2*k + 1];
        sPx[k] = pack2(pa.x, pb.x); sPy[k] = pack2(pa.y, pb.y); sPz[k] = pack2(pa.z, pb.z);
        sNx[k] = pack2(na.x, nb.x); sNy[k] = pack2(na.y, nb.y); sNz[k] = pack2(na.z, nb.z);
    }
    for (int k = tid; k < cnt * (HDIM / 4); k += TILE_I) {
        int r = k >> 3, q = k & 7;
        float4 v = ((const float4*)g_z)[(j0 + r) * (HDIM / 4) + q];
        int c0 = q * 4;
        int g0 = c0 >> 3;
        float4 o;
        o.x = (v.x - smu[g0]) * srs[g0] * gamma[c0]     + beta[c0];
        o.y = (v.y - smu[g0]) * srs[g0] * gamma[c0 + 1] + beta[c0 + 1];
        int g1 = (c0 + 2) >> 3;
        o.z = (v.z - smu[g1]) * srs[g1] * gamma[c0 + 2] + beta[c0 + 2];
        o.w = (v.w - smu[g1]) * srs[g1] * gamma[c0 + 3] + beta[c0 + 3];
        ((float4*)sF)[k] = o;
    }
    __syncthreads();

    int half  = tid >> 6;
    int iloc  = tid & 63;
    int i     = blockIdx.x * 64 + iloc;
    int hbase = half * 16;

    // packed (broadcast) per-i geometry
    float4 p4 = g_pts4[i];
    float4 n4 = g_nrm4[i];
    ull npx = pack2(-p4.x, -p4.x), npy = pack2(-p4.y, -p4.y), npz = pack2(-p4.z, -p4.z);
    ull nx2 = pack2(n4.x, n4.x),   ny2 = pack2(n4.y, n4.y),   nz2 = pack2(n4.z, n4.z);
    ull u2[9];
#pragma unroll
    for (int k = 0; k < 9; k++) { float v = nuv[i * 9 + k]; u2[k] = pack2(v, v); }
    const ull NEG1 = 0xBF800000BF800000ull;   // (-1,-1)
    const ull TWO2 = 0x4000000040000000ull;   // ( 2, 2)

    // register-resident packed A2 slab: a2p[hp][c] = (A2[2hp][c], A2[2hp+1][c])
    ull a2p[64];
    ull b2p[8];
#pragma unroll
    for (int hp = 0; hp < 8; hp++) {
        int h0 = hbase + 2 * hp;
        float4 r0a = ((const float4*)A2)[h0 * 2];
        float4 r0b = ((const float4*)A2)[h0 * 2 + 1];
        float4 r1a = ((const float4*)A2)[(h0 + 1) * 2];
        float4 r1b = ((const float4*)A2)[(h0 + 1) * 2 + 1];
        a2p[hp * 8 + 0] = pack2(r0a.x, r1a.x);
        a2p[hp * 8 + 1] = pack2(r0a.y, r1a.y);
        a2p[hp * 8 + 2] = pack2(r0a.z, r1a.z);
        a2p[hp * 8 + 3] = pack2(r0a.w, r1a.w);
        a2p[hp * 8 + 4] = pack2(r0b.x, r1b.x);
        a2p[hp * 8 + 5] = pack2(r0b.y, r1b.y);
        a2p[hp * 8 + 6] = pack2(r0b.z, r1b.z);
        a2p[hp * 8 + 7] = pack2(r0b.w, r1b.w);
        b2p[hp] = pack2(B2[h0], B2[h0 + 1]);
    }

    ull acc[8];
#pragma unroll
    for (int hp = 0; hp < 8; hp++) acc[hp] = 0ull;

    for (int jp = 0; jp < npairs; jp++) {
        // packed preamble for (j0=2jp, j1=2jp+1)
        ull dxp = add2(sPx[jp], npx);
        ull dyp = add2(sPy[jp], npy);
        ull dzp = add2(sPz[jp], npz);
        ull sq2  = fma2(dxp, dxp, fma2(dyp, dyp, mul2(dzp, dzp)));
        ull dot2 = fma2(nx2, sNx[jp], fma2(ny2, sNy[jp], mul2(nz2, sNz[jp])));
        ull t2   = fma2(dot2, NEG1, TWO2);             // 2 - dot
        ull arg2 = mul2(mul2(sq2, t2), negsign2(t2));  // -sq*t*t
        float2 av = unpack2(arg2);
        float w0 = __expf(av.x);
        float w1 = __expf(av.y);

        ull X0p = fma2(u2[0], dxp, fma2(u2[1], dyp, mul2(u2[2], dzp)));
        ull X1p = fma2(u2[3], dxp, fma2(u2[4], dyp, mul2(u2[5], dzp)));
        ull X2p = fma2(u2[6], dxp, fma2(u2[7], dyp, mul2(u2[8], dzp)));
        float2 X0v = unpack2(X0p), X1v = unpack2(X1p), X2v = unpack2(X2p);

#pragma unroll
        for (int sub = 0; sub < 2; sub++) {
            int j = 2 * jp + sub;
            float X0 = sub ? X0v.y : X0v.x;
            float X1 = sub ? X1v.y : X1v.x;
            float X2 = sub ? X2v.y : X2v.x;
            float w  = sub ? w1 : w0;
            ull X0b = pack2(X0, X0), X1b = pack2(X1, X1), X2b = pack2(X2, X2);
            ull w2  = pack2(w, w);

            // cut layer packed across (c,c+1); relu via FMNMX (ALU pipe)
            ull xcb[8];
#pragma unroll
            for (int q = 0; q < 4; q++) {
                ull s = fma2(sA1p[q], X0b, fma2(sA1p[4 + q], X1b, fma2(sA1p[8 + q], X2b, sA1p[12 + q])));
                float2 v = unpack2(s);
                v.x = fmaxf(v.x, 0.f);
                v.y = fmaxf(v.y, 0.f);
                xcb[2*q]     = pack2(v.x, v.x);
                xcb[2*q + 1] = pack2(v.y, v.y);
            }

            const ulonglong2* frow = (const ulonglong2*)&sF[j][hbase];
#pragma unroll
            for (int q2 = 0; q2 < 4; q2++) {
                ulonglong2 fq = frow[q2];
#pragma unroll
                for (int hh = 0; hh < 2; hh++) {
                    int hp = 2 * q2 + hh;
                    ull wf = mul2(w2, hh ? fq.y : fq.x);
                    const ull* ar = a2p + hp * 8;
                    ull s = b2p[hp];
#pragma unroll
                    for (int c = 0; c < 8; c++) s = fma2(ar[c], xcb[c], s);
                    s = relu2(s);
                    acc[hp] = fma2(s, wf, acc[hp]);
                }
            }
        }
    }

    ulonglong2* outp = (ulonglong2*)&g_partial[blockIdx.y][i * HDIM + hbase];
#pragma unroll
    for (int q = 0; q < 4; q++) {
        ulonglong2 v; v.x = acc[2*q]; v.y = acc[2*q+1];
        outp[q] = v;
    }
}

// ---------------- parallel reduce of partials (scalar: 65K threads) ----------------
__global__ void k_reduce() {
    int idx = blockIdx.x * blockDim.x + threadIdx.x;
    float s = g_partial[0][idx];
#pragma unroll
    for (int p = 1; p < JSPLIT; p++) s += g_partial[p][idx];
    g_mid[idx] = s;
}

// ---------------- net_out: warp per point ----------------
__global__ void k_netout(const float* __restrict__ W1, const float* __restrict__ b1,
                         const float* __restrict__ W2, const float* __restrict__ b2) {
    __shared__ float sW1t[HDIM * HDIM], sW2t[HDIM * HDIM], sb1[HDIM], sb2[HDIM];
    int tid = threadIdx.x;
    for (int k = tid; k < HDIM * HDIM; k += 256) {
        int h = k >> 5, c = k & 31;
        sW1t[c * HDIM + h] = W1[k];
        sW2t[c * HDIM + h] = W2[k];
    }
    if (tid < HDIM) { sb1[tid] = b1[tid]; sb2[tid] = b2[tid]; }
    __syncthreads();

    int n    = blockIdx.x * 8 + (tid >> 5);
    int lane = tid & 31;

    float xi = g_mid[n * HDIM + lane];

    float acc = sb1[lane];
#pragma unroll
    for (int c = 0; c < HDIM; c++)
        acc = fmaf(sW1t[c * HDIM + lane], __shfl_sync(0xffffffffu, xi, c), acc);
    float z1 = leakyf(acc);

    acc = sb2[lane];
#pragma unroll
    for (int c = 0; c < HDIM; c++)
        acc = fmaf(sW2t[c * HDIM + lane], __shfl_sync(0xffffffffu, z1, c), acc);
    g_z[n * HDIM + lane] = leakyf(acc);
}

// ---------------- launch ----------------
extern "C" void kernel_launch(void* const* d_in, const int* in_sizes, int n_in,
                              void* d_out, int out_size) {
    const float* points  = (const float*)d_in[0];
    const float* nuv     = (const float*)d_in[1];
    const float* feats   = (const float*)d_in[2];
    const float* W_in1   = (const float*)d_in[3];
    const float* b_in1   = (const float*)d_in[4];
    const float* W_in2   = (const float*)d_in[5];
    const float* b_in2   = (const float*)d_in[6];
    const float* g_in_w  = (const float*)d_in[7];
    const float* g_in_b  = (const float*)d_in[8];
    const float* A1      = (const float*)d_in[9];
    const float* A2      = (const float*)d_in[10];
    const float* W_out1  = (const float*)d_in[11];
    const float* b_out1  = (const float*)d_in[12];
    const float* W_out2  = (const float*)d_in[13];
    const float* b_out2  = (const float*)d_in[14];
    const float* g_out_w = (const float*)d_in[15];
    const float* g_out_b = (const float*)d_in[16];
    const float* B1      = (const float*)d_in[17];
    const float* B2      = (const float*)d_in[18];

    float* p_z;
    cudaGetSymbolAddress((void**)&p_z, g_z);

    k_netin<<<NPTS / 8, 256>>>(points, nuv, feats, W_in1, b_in1, W_in2, b_in2);
    k_gstats<<<1, 1024>>>(p_z);
    k_pair<<<dim3(NPTS / 64, JSPLIT), TILE_I>>>(nuv, A1, B1, A2, B2, g_in_w, g_in_b);
    k_reduce<<<(NPTS * HDIM) / 256, 256>>>();
    k_netout<<<NPTS / 8, 256>>>(W_out1, b_out1, W_out2, b_out2);
    k_gstats<<<1, 1024>>>(p_z);
    k_gnorm<<<(NPTS * HDIM) / 256, 256>>>(p_z, g_out_w, g_out_b, (float*)d_out);
}

// round 9
// speedup vs baseline: 1.0423x; 1.0423x over previous
#include <cuda_runtime.h>
#include <math.h>

#define NPTS   2048
#define IDIM   16
#define HDIM   32
#define JSPLIT 9
#define JCHUNK 228          // 8*228 + 224 = 2048
#define TILE_I 128

typedef unsigned long long ull;

// ---------------- device scratch ----------------
__device__ float4 g_pts4[NPTS];
__device__ float4 g_nrm4[NPTS];
__device__ float  g_z   [NPTS * HDIM];
__device__ float  g_partial[JSPLIT][NPTS * HDIM];
__device__ float  g_stats[8];   // mu[0..3], rstd[4..7]

__device__ __forceinline__ float leakyf(float x) { return x >= 0.f ? x : 0.2f * x; }

// ---------------- packed f32x2 (native 64-bit regs, sm_103a) ----------------
__device__ __forceinline__ ull fma2(ull a, ull b, ull c) {
    ull d; asm("fma.rn.f32x2 %0, %1, %2, %3;" : "=l"(d) : "l"(a), "l"(b), "l"(c)); return d;
}
__device__ __forceinline__ ull mul2(ull a, ull b) {
    ull d; asm("mul.rn.f32x2 %0, %1, %2;" : "=l"(d) : "l"(a), "l"(b)); return d;
}
__device__ __forceinline__ ull pack2(float lo, float hi) {
    ull d; asm("mov.b64 %0, {%1, %2};" : "=l"(d) : "f"(lo), "f"(hi)); return d;
}
__device__ __forceinline__ float2 unpack2(ull a) {
    float2 v; asm("mov.b64 {%0, %1}, %2;" : "=f"(v.x), "=f"(v.y) : "l"(a)); return v;
}
// relu on a packed pair via 2x FMNMX (ALU pipe) -- keeps the FMA pipe clear
__device__ __forceinline__ ull relu2(ull a) {
    float2 v = unpack2(a);
    v.x = fmaxf(v.x, 0.f);
    v.y = fmaxf(v.y, 0.f);
    return pack2(v.x, v.y);
}

// ---------------- net_in: warp per point + prep ----------------
__global__ void k_netin(const float* __restrict__ points, const float* __restrict__ nuv,
                        const float* __restrict__ x,
                        const float* __restrict__ W1, const float* __restrict__ b1,
                        const float* __restrict__ W2, const float* __restrict__ b2) {
    __shared__ float sW1t[IDIM * HDIM];   // [c][h]
    __shared__ float sW2t[HDIM * HDIM];   // [c][h]
    __shared__ float sb1[HDIM], sb2[HDIM];
    int tid = threadIdx.x;
    for (int k = tid; k < HDIM * IDIM; k += 256) {
        int h = k / IDIM, c = k % IDIM;
        sW1t[c * HDIM + h] = W1[k];
    }
    for (int k = tid; k < HDIM * HDIM; k += 256) {
        int h = k >> 5, c = k & 31;
        sW2t[c * HDIM + h] = W2[k];
    }
    if (tid < HDIM) { sb1[tid] = b1[tid]; sb2[tid] = b2[tid]; }
    __syncthreads();

    int n    = blockIdx.x * 8 + (tid >> 5);
    int lane = tid & 31;

    if (lane == 0) {
        const float s = 0.07856742013183862f;  // 1/(sqrt(2)*9)
        g_pts4[n] = make_float4(points[n*3] * s, points[n*3+1] * s, points[n*3+2] * s, 0.f);
        g_nrm4[n] = make_float4(nuv[n*9], nuv[n*9+1], nuv[n*9+2], 0.f);
    }

    float xi = (lane < IDIM) ? x[n * IDIM + lane] : 0.f;

    float acc = sb1[lane];
#pragma unroll
    for (int c = 0; c < IDIM; c++)
        acc = fmaf(sW1t[c * HDIM + lane], __shfl_sync(0xffffffffu, xi, c), acc);
    float z1 = leakyf(acc);

    acc = sb2[lane];
#pragma unroll
    for (int c = 0; c < HDIM; c++)
        acc = fmaf(sW2t[c * HDIM + lane], __shfl_sync(0xffffffffu, z1, c), acc);
    g_z[n * HDIM + lane] = leakyf(acc);
}

// ---------------- group-norm stats (fp32 inner, fp64 final) ----------------
__global__ void k_gstats(const float* __restrict__ z) {
    __shared__ float sh_s[1024], sh_q[1024];
    __shared__ double sd_s[32], sd_q[32];
    int tid = threadIdx.x;
    int c = tid & 31;
    int r0 = tid >> 5;
    float s = 0.f, q = 0.f;
    for (int it = 0; it < NPTS / 32; it++) {
        float v = z[(r0 + 32 * it) * HDIM + c];
        s += v;
        q = fmaf(v, v, q);
    }
    sh_s[tid] = s; sh_q[tid] = q;
    __syncthreads();
    if (tid < 32) {
        double S = 0.0, Q = 0.0;
        for (int m = 0; m < 32; m++) { S += (double)sh_s[tid + 32 * m]; Q += (double)sh_q[tid + 32 * m]; }
        sd_s[tid] = S; sd_q[tid] = Q;
    }
    __syncthreads();
    if (tid < 4) {
        double S = 0.0, Q = 0.0;
        for (int cc = tid * 8; cc < tid * 8 + 8; cc++) { S += sd_s[cc]; Q += sd_q[cc]; }
        double cntd = (double)NPTS * 8.0;
        double mu = S / cntd;
        double var = Q / cntd - mu * mu;
        g_stats[tid]     = (float)mu;
        g_stats[4 + tid] = (float)(1.0 / sqrt(var + 1e-5));
    }
}

// ---------------- apply group norm (final output) ----------------
__global__ void k_gnorm(const float* __restrict__ z, const float* __restrict__ gamma,
                        const float* __restrict__ beta, float* __restrict__ out) {
    int idx = blockIdx.x * blockDim.x + threadIdx.x;
    if (idx >= NPTS * HDIM) return;
    int c = idx & (HDIM - 1);
    int g = c >> 3;
    out[idx] = (z[idx] - g_stats[g]) * g_stats[4 + g] * gamma[c] + beta[c];
}

// ---------------- pairwise interaction: packed f32x2, A2+A1 register-resident ----------------
__global__ void __launch_bounds__(TILE_I, 2)
k_pair(const float* __restrict__ nuv,
       const float* __restrict__ A1, const float* __restrict__ B1,
       const float* __restrict__ A2, const float* __restrict__ B2,
       const float* __restrict__ gamma, const float* __restrict__ beta) {
    __shared__ float4 sP[JCHUNK], sN[JCHUNK];
    __shared__ __align__(16) float sF[JCHUNK][HDIM];
    __shared__ float smu[4], srs[4];

    int tid = threadIdx.x;
    int j0  = blockIdx.y * JCHUNK;
    int cnt = min(JCHUNK, NPTS - j0);   // 228 or 224, always even

    if (tid < 4) { smu[tid] = g_stats[tid]; srs[tid] = g_stats[4 + tid]; }
    __syncthreads();   // smu/srs before sF fill

    for (int k = tid; k < cnt; k += TILE_I) { sP[k] = g_pts4[j0 + k]; sN[k] = g_nrm4[j0 + k]; }
    for (int k = tid; k < cnt * (HDIM / 4); k += TILE_I) {
        int r = k >> 3, q = k & 7;
        float4 v = ((const float4*)g_z)[(j0 + r) * (HDIM / 4) + q];
        int c0 = q * 4;
        int g0 = c0 >> 3;
        float4 o;
        o.x = (v.x - smu[g0]) * srs[g0] * gamma[c0]     + beta[c0];
        o.y = (v.y - smu[g0]) * srs[g0] * gamma[c0 + 1] + beta[c0 + 1];
        int g1 = (c0 + 2) >> 3;
        o.z = (v.z - smu[g1]) * srs[g1] * gamma[c0 + 2] + beta[c0 + 2];
        o.w = (v.w - smu[g1]) * srs[g1] * gamma[c0 + 3] + beta[c0 + 3];
        ((float4*)sF)[k] = o;
    }
    __syncthreads();

    int half  = tid >> 6;
    int iloc  = tid & 63;
    int i     = blockIdx.x * 64 + iloc;
    int hbase = half * 16;

    float4 p4 = g_pts4[i];
    float4 n4 = g_nrm4[i];
    float u[9];
#pragma unroll
    for (int k = 0; k < 9; k++) u[k] = nuv[i * 9 + k];

    // A1/B1 packed across cut pairs, register-resident
    ull a1p[16];
#pragma unroll
    for (int comp = 0; comp < 3; comp++)
#pragma unroll
        for (int q = 0; q < 4; q++)
            a1p[comp * 4 + q] = pack2(A1[(2 * q) * 3 + comp], A1[(2 * q + 1) * 3 + comp]);
#pragma unroll
    for (int q = 0; q < 4; q++) a1p[12 + q] = pack2(B1[2 * q], B1[2 * q + 1]);

    // register-resident packed A2 slab: a2p[hp][c] = (A2[2hp][c], A2[2hp+1][c])
    ull a2p[64];
    ull b2p[8];
#pragma unroll
    for (int hp = 0; hp < 8; hp++) {
        int h0 = hbase + 2 * hp;
        float4 r0a = ((const float4*)A2)[h0 * 2];
        float4 r0b = ((const float4*)A2)[h0 * 2 + 1];
        float4 r1a = ((const float4*)A2)[(h0 + 1) * 2];
        float4 r1b = ((const float4*)A2)[(h0 + 1) * 2 + 1];
        a2p[hp * 8 + 0] = pack2(r0a.x, r1a.x);
        a2p[hp * 8 + 1] = pack2(r0a.y, r1a.y);
        a2p[hp * 8 + 2] = pack2(r0a.z, r1a.z);
        a2p[hp * 8 + 3] = pack2(r0a.w, r1a.w);
        a2p[hp * 8 + 4] = pack2(r0b.x, r1b.x);
        a2p[hp * 8 + 5] = pack2(r0b.y, r1b.y);
        a2p[hp * 8 + 6] = pack2(r0b.z, r1b.z);
        a2p[hp * 8 + 7] = pack2(r0b.w, r1b.w);
        b2p[hp] = pack2(B2[h0], B2[h0 + 1]);
    }

    ull acc[8];
#pragma unroll
    for (int hp = 0; hp < 8; hp++) acc[hp] = 0ull;

#pragma unroll 2
    for (int j = 0; j < cnt; j++) {
        float4 pj = sP[j], nj = sN[j];
        float dx = pj.x - p4.x, dy = pj.y - p4.y, dz = pj.z - p4.z;
        float sq  = fmaf(dx, dx, fmaf(dy, dy, dz * dz));
        float dot = fmaf(n4.x, nj.x, fmaf(n4.y, nj.y, n4.z * nj.z));
        float t   = 2.f - dot;
        float w   = __expf(-(sq * t) * t);
        ull  w2   = pack2(w, w);

        float X0 = fmaf(u[0], dx, fmaf(u[1], dy, u[2] * dz));
        float X1 = fmaf(u[3], dx, fmaf(u[4], dy, u[5] * dz));
        float X2 = fmaf(u[6], dx, fmaf(u[7], dy, u[8] * dz));
        ull X0b = pack2(X0, X0), X1b = pack2(X1, X1), X2b = pack2(X2, X2);

        // cut layer packed across (c,c+1); relu via FMNMX (ALU pipe)
        ull xcb[8];
#pragma unroll
        for (int q = 0; q < 4; q++) {
            ull s = fma2(a1p[q], X0b, fma2(a1p[4 + q], X1b, fma2(a1p[8 + q], X2b, a1p[12 + q])));
            float2 v = unpack2(s);
            v.x = fmaxf(v.x, 0.f);
            v.y = fmaxf(v.y, 0.f);
            xcb[2*q]     = pack2(v.x, v.x);
            xcb[2*q + 1] = pack2(v.y, v.y);
        }

        const ulonglong2* frow = (const ulonglong2*)&sF[j][hbase];
#pragma unroll
        for (int q2 = 0; q2 < 4; q2++) {
            ulonglong2 fq = frow[q2];
#pragma unroll
            for (int hh = 0; hh < 2; hh++) {
                int hp = 2 * q2 + hh;
                ull wf = mul2(w2, hh ? fq.y : fq.x);
                const ull* ar = a2p + hp * 8;
                ull s = b2p[hp];
#pragma unroll
                for (int c = 0; c < 8; c++) s = fma2(ar[c], xcb[c], s);
                s = relu2(s);                    // 2x FMNMX on ALU pipe
                acc[hp] = fma2(s, wf, acc[hp]);
            }
        }
    }

    ulonglong2* outp = (ulonglong2*)&g_partial[blockIdx.y][i * HDIM + hbase];
#pragma unroll
    for (int q = 0; q < 4; q++) {
        ulonglong2 v; v.x = acc[2*q]; v.y = acc[2*q+1];
        outp[q] = v;
    }
}

// ---------------- reduce(9 partials) + net_out fused: warp per point ----------------
__global__ void k_netout(const float* __restrict__ W1, const float* __restrict__ b1,
                         const float* __restrict__ W2, const float* __restrict__ b2) {
    __shared__ float sW1t[HDIM * HDIM], sW2t[HDIM * HDIM], sb1[HDIM], sb2[HDIM];
    int tid = threadIdx.x;
    for (int k = tid; k < HDIM * HDIM; k += 256) {
        int h = k >> 5, c = k & 31;
        sW1t[c * HDIM + h] = W1[k];
        sW2t[c * HDIM + h] = W2[k];
    }
    if (tid < HDIM) { sb1[tid] = b1[tid]; sb2[tid] = b2[tid]; }
    __syncthreads();

    int n    = blockIdx.x * 8 + (tid >> 5);
    int lane = tid & 31;

    // 9 independent loads (MLP=9) -> latency mostly overlapped
    float xi = 0.f;
#pragma unroll
    for (int p = 0; p < JSPLIT; p++) xi += g_partial[p][n * HDIM + lane];

    float acc = sb1[lane];
#pragma unroll
    for (int c = 0; c < HDIM; c++)
        acc = fmaf(sW1t[c * HDIM + lane], __shfl_sync(0xffffffffu, xi, c), acc);
    float z1 = leakyf(acc);

    acc = sb2[lane];
#pragma unroll
    for (int c = 0; c < HDIM; c++)
        acc = fmaf(sW2t[c * HDIM + lane], __shfl_sync(0xffffffffu, z1, c), acc);
    g_z[n * HDIM + lane] = leakyf(acc);
}

// ---------------- launch ----------------
extern "C" void kernel_launch(void* const* d_in, const int* in_sizes, int n_in,
                              void* d_out, int out_size) {
    const float* points  = (const float*)d_in[0];
    const float* nuv     = (const float*)d_in[1];
    const float* feats   = (const float*)d_in[2];
    const float* W_in1   = (const float*)d_in[3];
    const float* b_in1   = (const float*)d_in[4];
    const float* W_in2   = (const float*)d_in[5];
    const float* b_in2   = (const float*)d_in[6];
    const float* g_in_w  = (const float*)d_in[7];
    const float* g_in_b  = (const float*)d_in[8];
    const float* A1      = (const float*)d_in[9];
    const float* A2      = (const float*)d_in[10];
    const float* W_out1  = (const float*)d_in[11];
    const float* b_out1  = (const float*)d_in[12];
    const float* W_out2  = (const float*)d_in[13];
    const float* b_out2  = (const float*)d_in[14];
    const float* g_out_w = (const float*)d_in[15];
    const float* g_out_b = (const float*)d_in[16];
    const float* B1      = (const float*)d_in[17];
    const float* B2      = (const float*)d_in[18];

    float* p_z;
    cudaGetSymbolAddress((void**)&p_z, g_z);

    k_netin<<<NPTS / 8, 256>>>(points, nuv, feats, W_in1, b_in1, W_in2, b_in2);
    k_gstats<<<1, 1024>>>(p_z);
    k_pair<<<dim3(NPTS / 64, JSPLIT), TILE_I>>>(nuv, A1, B1, A2, B2, g_in_w, g_in_b);
    k_netout<<<NPTS / 8, 256>>>(W_out1, b_out1, W_out2, b_out2);
    k_gstats<<<1, 1024>>>(p_z);
    k_gnorm<<<(NPTS * HDIM) / 256, 256>>>(p_z, g_out_w, g_out_b, (float*)d_out);
}

// round 10
// speedup vs baseline: 1.0876x; 1.0435x over previous
#include <cuda_runtime.h>
#include <math.h>

#define NPTS   2048
#define IDIM   16
#define HDIM   32
#define JSPLIT 9
#define JCHUNK 228          // 8*228 + 224 = 2048
#define TILE_I 128

typedef unsigned long long ull;

// ---------------- device scratch ----------------
__device__ float4 g_pts4[NPTS];
__device__ float4 g_nrm4[NPTS];
__device__ float  g_z   [NPTS * HDIM];
__device__ float  g_partial[JSPLIT][NPTS * HDIM];
__device__ float  g_stats[8];   // mu[0..3], rstd[4..7]

__device__ __forceinline__ float leakyf(float x) { return x >= 0.f ? x : 0.2f * x; }

// ---------------- packed f32x2 (native 64-bit regs, sm_103a) ----------------
__device__ __forceinline__ ull fma2(ull a, ull b, ull c) {
    ull d; asm("fma.rn.f32x2 %0, %1, %2, %3;" : "=l"(d) : "l"(a), "l"(b), "l"(c)); return d;
}
__device__ __forceinline__ ull mul2(ull a, ull b) {
    ull d; asm("mul.rn.f32x2 %0, %1, %2;" : "=l"(d) : "l"(a), "l"(b)); return d;
}
__device__ __forceinline__ ull pack2(float lo, float hi) {
    ull d; asm("mov.b64 %0, {%1, %2};" : "=l"(d) : "f"(lo), "f"(hi)); return d;
}
__device__ __forceinline__ float2 unpack2(ull a) {
    float2 v; asm("mov.b64 {%0, %1}, %2;" : "=f"(v.x), "=f"(v.y) : "l"(a)); return v;
}

// ---------------- net_in: warp per point + prep ----------------
__global__ void k_netin(const float* __restrict__ points, const float* __restrict__ nuv,
                        const float* __restrict__ x,
                        const float* __restrict__ W1, const float* __restrict__ b1,
                        const float* __restrict__ W2, const float* __restrict__ b2) {
    __shared__ float sW1t[IDIM * HDIM];   // [c][h]
    __shared__ float sW2t[HDIM * HDIM];   // [c][h]
    __shared__ float sb1[HDIM], sb2[HDIM];
    int tid = threadIdx.x;
    for (int k = tid; k < HDIM * IDIM; k += 256) {
        int h = k / IDIM, c = k % IDIM;
        sW1t[c * HDIM + h] = W1[k];
    }
    for (int k = tid; k < HDIM * HDIM; k += 256) {
        int h = k >> 5, c = k & 31;
        sW2t[c * HDIM + h] = W2[k];
    }
    if (tid < HDIM) { sb1[tid] = b1[tid]; sb2[tid] = b2[tid]; }
    __syncthreads();

    int n    = blockIdx.x * 8 + (tid >> 5);
    int lane = tid & 31;

    if (lane == 0) {
        const float s = 0.07856742013183862f;  // 1/(sqrt(2)*9)
        g_pts4[n] = make_float4(points[n*3] * s, points[n*3+1] * s, points[n*3+2] * s, 0.f);
        g_nrm4[n] = make_float4(nuv[n*9], nuv[n*9+1], nuv[n*9+2], 0.f);
    }

    float xi = (lane < IDIM) ? x[n * IDIM + lane] : 0.f;

    float acc = sb1[lane];
#pragma unroll
    for (int c = 0; c < IDIM; c++)
        acc = fmaf(sW1t[c * HDIM + lane], __shfl_sync(0xffffffffu, xi, c), acc);
    float z1 = leakyf(acc);

    acc = sb2[lane];
#pragma unroll
    for (int c = 0; c < HDIM; c++)
        acc = fmaf(sW2t[c * HDIM + lane], __shfl_sync(0xffffffffu, z1, c), acc);
    g_z[n * HDIM + lane] = leakyf(acc);
}

// ---------------- group-norm stats (fp32 inner, fp64 final) ----------------
__global__ void k_gstats(const float* __restrict__ z) {
    __shared__ float sh_s[1024], sh_q[1024];
    __shared__ double sd_s[32], sd_q[32];
    int tid = threadIdx.x;
    int c = tid & 31;
    int r0 = tid >> 5;
    float s = 0.f, q = 0.f;
    for (int it = 0; it < NPTS / 32; it++) {
        float v = z[(r0 + 32 * it) * HDIM + c];
        s += v;
        q = fmaf(v, v, q);
    }
    sh_s[tid] = s; sh_q[tid] = q;
    __syncthreads();
    if (tid < 32) {
        double S = 0.0, Q = 0.0;
        for (int m = 0; m < 32; m++) { S += (double)sh_s[tid + 32 * m]; Q += (double)sh_q[tid + 32 * m]; }
        sd_s[tid] = S; sd_q[tid] = Q;
    }
    __syncthreads();
    if (tid < 4) {
        double S = 0.0, Q = 0.0;
        for (int cc = tid * 8; cc < tid * 8 + 8; cc++) { S += sd_s[cc]; Q += sd_q[cc]; }
        double cntd = (double)NPTS * 8.0;
        double mu = S / cntd;
        double var = Q / cntd - mu * mu;
        g_stats[tid]     = (float)mu;
        g_stats[4 + tid] = (float)(1.0 / sqrt(var + 1e-5));
    }
}

// ---------------- apply group norm (final output) ----------------
__global__ void k_gnorm(const float* __restrict__ z, const float* __restrict__ gamma,
                        const float* __restrict__ beta, float* __restrict__ out) {
    int idx = blockIdx.x * blockDim.x + threadIdx.x;
    if (idx >= NPTS * HDIM) return;
    int c = idx & (HDIM - 1);
    int g = c >> 3;
    out[idx] = (z[idx] - g_stats[g]) * g_stats[4 + g] * gamma[c] + beta[c];
}

// ---------------- pairwise interaction: folded frame (M=A1@u), dual packed dots ----------------
__global__ void __launch_bounds__(TILE_I, 2)
k_pair(const float* __restrict__ nuv,
       const float* __restrict__ A1, const float* __restrict__ B1,
       const float* __restrict__ A2, const float* __restrict__ B2,
       const float* __restrict__ gamma, const float* __restrict__ beta) {
    __shared__ ulonglong2 sDa[JCHUNK];   // {(pjx,njx),(pjy,njy)}
    __shared__ ulonglong2 sDb[JCHUNK];   // {(pjz,njz),(|pj|^2, 0)}
    __shared__ ulonglong2 sBa[JCHUNK];   // {(pjx,pjx),(pjy,pjy)}
    __shared__ ull        sBz[JCHUNK];   // (pjz,pjz)
    __shared__ __align__(16) float sF[JCHUNK][HDIM];
    __shared__ float smu[4], srs[4];

    int tid = threadIdx.x;
    int j0  = blockIdx.y * JCHUNK;
    int cnt = min(JCHUNK, NPTS - j0);

    if (tid < 4) { smu[tid] = g_stats[tid]; srs[tid] = g_stats[4 + tid]; }
    __syncthreads();   // smu/srs before sF fill

    for (int k = tid; k < cnt; k += TILE_I) {
        float4 pj = g_pts4[j0 + k];
        float4 nj = g_nrm4[j0 + k];
        float w2j = fmaf(pj.x, pj.x, fmaf(pj.y, pj.y, pj.z * pj.z));
        ulonglong2 da; da.x = pack2(pj.x, nj.x); da.y = pack2(pj.y, nj.y);
        ulonglong2 db; db.x = pack2(pj.z, nj.z); db.y = pack2(w2j, 0.f);
        ulonglong2 ba; ba.x = pack2(pj.x, pj.x); ba.y = pack2(pj.y, pj.y);
        sDa[k] = da; sDb[k] = db; sBa[k] = ba; sBz[k] = pack2(pj.z, pj.z);
    }
    for (int k = tid; k < cnt * (HDIM / 4); k += TILE_I) {
        int r = k >> 3, q = k & 7;
        float4 v = ((const float4*)g_z)[(j0 + r) * (HDIM / 4) + q];
        int c0 = q * 4;
        int g0 = c0 >> 3;
        float4 o;
        o.x = (v.x - smu[g0]) * srs[g0] * gamma[c0]     + beta[c0];
        o.y = (v.y - smu[g0]) * srs[g0] * gamma[c0 + 1] + beta[c0 + 1];
        int g1 = (c0 + 2) >> 3;
        o.z = (v.z - smu[g1]) * srs[g1] * gamma[c0 + 2] + beta[c0 + 2];
        o.w = (v.w - smu[g1]) * srs[g1] * gamma[c0 + 3] + beta[c0 + 3];
        ((float4*)sF)[k] = o;
    }
    __syncthreads();

    int half  = tid >> 6;
    int iloc  = tid & 63;
    int i     = blockIdx.x * 64 + iloc;
    int hbase = half * 16;

    float4 p4 = g_pts4[i];
    float4 n4 = g_nrm4[i];
    float ci = fmaf(p4.x, p4.x, fmaf(p4.y, p4.y, p4.z * p4.z));   // |p_i|^2
    ull pin0 = pack2(p4.x, n4.x), pin1 = pack2(p4.y, n4.y), pin2 = pack2(p4.z, n4.z);

    // M = A1 @ u_i (8x3), b1i = B1 - M . p_i  -> cut = M . p_j + b1i
    float M[24], b1i[8];
    {
        float u[9];
#pragma unroll
        for (int k = 0; k < 9; k++) u[k] = nuv[i * 9 + k];
#pragma unroll
        for (int k = 0; k < 8; k++) {
            float a0 = A1[k * 3], a1 = A1[k * 3 + 1], a2 = A1[k * 3 + 2];
#pragma unroll
            for (int c = 0; c < 3; c++)
                M[k * 3 + c] = fmaf(a0, u[c], fmaf(a1, u[3 + c], a2 * u[6 + c]));
            b1i[k] = B1[k] - (fmaf(M[k*3], p4.x, fmaf(M[k*3+1], p4.y, M[k*3+2] * p4.z)));
        }
    }
    ull m[12], b1ip[4];
#pragma unroll
    for (int comp = 0; comp < 3; comp++)
#pragma unroll
        for (int q = 0; q < 4; q++)
            m[comp * 4 + q] = pack2(M[(2*q) * 3 + comp], M[(2*q+1) * 3 + comp]);
#pragma unroll
    for (int q = 0; q < 4; q++) b1ip[q] = pack2(b1i[2*q], b1i[2*q+1]);

    // register-resident packed A2 slab: a2p[hp][c] = (A2[2hp][c], A2[2hp+1][c])
    ull a2p[64];
    ull b2p[8];
#pragma unroll
    for (int hp = 0; hp < 8; hp++) {
        int h0 = hbase + 2 * hp;
        float4 r0a = ((const float4*)A2)[h0 * 2];
        float4 r0b = ((const float4*)A2)[h0 * 2 + 1];
        float4 r1a = ((const float4*)A2)[(h0 + 1) * 2];
        float4 r1b = ((const float4*)A2)[(h0 + 1) * 2 + 1];
        a2p[hp * 8 + 0] = pack2(r0a.x, r1a.x);
        a2p[hp * 8 + 1] = pack2(r0a.y, r1a.y);
        a2p[hp * 8 + 2] = pack2(r0a.z, r1a.z);
        a2p[hp * 8 + 3] = pack2(r0a.w, r1a.w);
        a2p[hp * 8 + 4] = pack2(r0b.x, r1b.x);
        a2p[hp * 8 + 5] = pack2(r0b.y, r1b.y);
        a2p[hp * 8 + 6] = pack2(r0b.z, r1b.z);
        a2p[hp * 8 + 7] = pack2(r0b.w, r1b.w);
        b2p[hp] = pack2(B2[h0], B2[h0 + 1]);
    }

    ull acc[8];
#pragma unroll
    for (int hp = 0; hp < 8; hp++) acc[hp] = 0ull;

#pragma unroll 2
    for (int j = 0; j < cnt; j++) {
        ulonglong2 da = sDa[j];
        ulonglong2 db = sDb[j];
        // dual dot: (p_i . p_j, n_i . n_j) in one packed chain
        ull dual = fma2(pin0, da.x, fma2(pin1, da.y, mul2(pin2, db.x)));
        float2 dd = unpack2(dual);
        float w2j = unpack2(db.y).x;
        float sq  = fmaf(-2.f, dd.x, ci + w2j);
        float t   = 2.f - dd.y;
        float w   = __expf(-(sq * t) * t);
        ull  w2   = pack2(w, w);

        // cut layer: M.p_j + b1i, packed across (c,c+1); relu via FMNMX (ALU)
        ulonglong2 ba = sBa[j];
        ull bz = sBz[j];
        ull xcb[8];
#pragma unroll
        for (int q = 0; q < 4; q++) {
            ull s = fma2(m[q], ba.x, fma2(m[4 + q], ba.y, fma2(m[8 + q], bz, b1ip[q])));
            float2 v = unpack2(s);
            v.x = fmaxf(v.x, 0.f);
            v.y = fmaxf(v.y, 0.f);
            xcb[2*q]     = pack2(v.x, v.x);
            xcb[2*q + 1] = pack2(v.y, v.y);
        }

        const ulonglong2* frow = (const ulonglong2*)&sF[j][hbase];
#pragma unroll
        for (int q2 = 0; q2 < 4; q2++) {
            ulonglong2 fq = frow[q2];
#pragma unroll
            for (int hh = 0; hh < 2; hh++) {
                int hp = 2 * q2 + hh;
                ull wf = mul2(w2, hh ? fq.y : fq.x);
                const ull* ar = a2p + hp * 8;
                ull s = b2p[hp];
#pragma unroll
                for (int c = 0; c < 8; c++) s = fma2(ar[c], xcb[c], s);
                float2 v = unpack2(s);          // relu via 2x FMNMX (ALU pipe)
                v.x = fmaxf(v.x, 0.f);
                v.y = fmaxf(v.y, 0.f);
                acc[hp] = fma2(pack2(v.x, v.y), wf, acc[hp]);
            }
        }
    }

    ulonglong2* outp = (ulonglong2*)&g_partial[blockIdx.y][i * HDIM + hbase];
#pragma unroll
    for (int q = 0; q < 4; q++) {
        ulonglong2 v; v.x = acc[2*q]; v.y = acc[2*q+1];
        outp[q] = v;
    }
}

// ---------------- reduce(9 partials) + net_out fused: warp per point ----------------
__global__ void k_netout(const float* __restrict__ W1, const float* __restrict__ b1,
                         const float* __restrict__ W2, const float* __restrict__ b2) {
    __shared__ float sW1t[HDIM * HDIM], sW2t[HDIM * HDIM], sb1[HDIM], sb2[HDIM];
    int tid = threadIdx.x;
    for (int k = tid; k < HDIM * HDIM; k += 256) {
        int h = k >> 5, c = k & 31;
        sW1t[c * HDIM + h] = W1[k];
        sW2t[c * HDIM + h] = W2[k];
    }
    if (tid < HDIM) { sb1[tid] = b1[tid]; sb2[tid] = b2[tid]; }
    __syncthreads();

    int n    = blockIdx.x * 8 + (tid >> 5);
    int lane = tid & 31;

    float xi = 0.f;
#pragma unroll
    for (int p = 0; p < JSPLIT; p++) xi += g_partial[p][n * HDIM + lane];

    float acc = sb1[lane];
#pragma unroll
    for (int c = 0; c < HDIM; c++)
        acc = fmaf(sW1t[c * HDIM + lane], __shfl_sync(0xffffffffu, xi, c), acc);
    float z1 = leakyf(acc);

    acc = sb2[lane];
#pragma unroll
    for (int c = 0; c < HDIM; c++)
        acc = fmaf(sW2t[c * HDIM + lane], __shfl_sync(0xffffffffu, z1, c), acc);
    g_z[n * HDIM + lane] = leakyf(acc);
}

// ---------------- launch ----------------
extern "C" void kernel_launch(void* const* d_in, const int* in_sizes, int n_in,
                              void* d_out, int out_size) {
    const float* points  = (const float*)d_in[0];
    const float* nuv     = (const float*)d_in[1];
    const float* feats   = (const float*)d_in[2];
    const float* W_in1   = (const float*)d_in[3];
    const float* b_in1   = (const float*)d_in[4];
    const float* W_in2   = (const float*)d_in[5];
    const float* b_in2   = (const float*)d_in[6];
    const float* g_in_w  = (const float*)d_in[7];
    const float* g_in_b  = (const float*)d_in[8];
    const float* A1      = (const float*)d_in[9];
    const float* A2      = (const float*)d_in[10];
    const float* W_out1  = (const float*)d_in[11];
    const float* b_out1  = (const float*)d_in[12];
    const float* W_out2  = (const float*)d_in[13];
    const float* b_out2  = (const float*)d_in[14];
    const float* g_out_w = (const float*)d_in[15];
    const float* g_out_b = (const float*)d_in[16];
    const float* B1      = (const float*)d_in[17];
    const float* B2      = (const float*)d_in[18];

    float* p_z;
    cudaGetSymbolAddress((void**)&p_z, g_z);

    k_netin<<<NPTS / 8, 256>>>(points, nuv, feats, W_in1, b_in1, W_in2, b_in2);
    k_gstats<<<1, 1024>>>(p_z);
    k_pair<<<dim3(NPTS / 64, JSPLIT), TILE_I>>>(nuv, A1, B1, A2, B2, g_in_w, g_in_b);
    k_netout<<<NPTS / 8, 256>>>(W_out1, b_out1, W_out2, b_out2);
    k_gstats<<<1, 1024>>>(p_z);
    k_gnorm<<<(NPTS * HDIM) / 256, 256>>>(p_z, g_out_w, g_out_b, (float*)d_out);
}